// round 15
// baseline (speedup 1.0000x reference)
#include <cuda_runtime.h>
#include <cuda_bf16.h>

#define B_   8
#define T0_  16384
#define T1_  16383
#define T2_  16382
#define TFIN 15360

typedef unsigned long long ULL;
typedef unsigned int uint32;

// -------- scratch (device globals; no allocation allowed) --------
__device__ __nv_bfloat16 g_xhi [(size_t)B_ * T0_ * 256];
__device__ __nv_bfloat16 g_xlo [(size_t)B_ * T0_ * 256];
__device__ float g_hA [(size_t)B_ * T2_ * 24];
__device__ float g_hB [(size_t)B_ * T2_ * 24];
__device__ __nv_bfloat16 g_a0hi[(size_t)B_ * TFIN * 128];
__device__ __nv_bfloat16 g_a0lo[(size_t)B_ * TFIN * 128];
__device__ __nv_bfloat16 g_a1hi[(size_t)B_ * TFIN * 256];
__device__ __nv_bfloat16 g_a1lo[(size_t)B_ * TFIN * 256];
// weights in k-paired bf16x2 word layout [K/2][N]
__device__ uint32 g_WcauHi[256 * 256], g_WcauLo[256 * 256];
__device__ uint32 g_Wg0Hi [256 * 48],  g_Wg0Lo [256 * 48];
__device__ uint32 g_Wf1Hi [64 * 256],  g_Wf1Lo [64 * 256];
__device__ uint32 g_Wf2Hi [128 * 256], g_Wf2Lo [128 * 256];

// -------- small helpers --------
__device__ __forceinline__ float sigmoidf_(float x) { return 1.f / (1.f + __expf(-x)); }
__device__ __forceinline__ float tanhf_(float x) {
    float e = __expf(2.f * x);
    return 1.f - 2.f / (e + 1.f);
}
// combined sigmoid(g)*tanh(f): 2 EX2 + 1 RCP, clamped (no inf/nan)
__device__ __forceinline__ float gatedact_(float g, float f) {
    g = fminf(fmaxf(g, -30.f), 30.f);
    f = fminf(fmaxf(f, -15.f), 15.f);
    float a = __expf(-g);
    float b = __expf(2.f * f);
    return __fdividef(b - 1.f, (1.f + a) * (b + 1.f));
}
__device__ __forceinline__ ULL pk2(float lo, float hi) {
    ULL r; asm("mov.b64 %0, {%1, %2};" : "=l"(r) : "f"(lo), "f"(hi)); return r;
}
__device__ __forceinline__ ULL dup2(float x) {
    ULL r; asm("mov.b64 %0, {%1, %1};" : "=l"(r) : "f"(x)); return r;
}
__device__ __forceinline__ float2 unpk2(ULL v) {
    float2 f; asm("mov.b64 {%0, %1}, %2;" : "=f"(f.x), "=f"(f.y) : "l"(v)); return f;
}
__device__ __forceinline__ void ffma2(ULL& d, ULL a, ULL b) {
    asm("fma.rn.f32x2 %0, %1, %2, %0;" : "+l"(d) : "l"(a), "l"(b));
}

// -------- cp.async --------
__device__ __forceinline__ void cp16(uint32 dst, const void* src, bool pred) {
    int sz = pred ? 16 : 0;
    asm volatile("cp.async.ca.shared.global [%0], [%1], 16, %2;"
                 :: "r"(dst), "l"(src), "r"(sz));
}
__device__ __forceinline__ void cpcommit() { asm volatile("cp.async.commit_group;"); }
template<int N> __device__ __forceinline__ void cpwait() {
    asm volatile("cp.async.wait_group %0;" :: "n"(N));
}

// -------- bf16 mma + ldmatrix --------
__device__ __forceinline__ void mma_bf16(float* c, const uint32* a, uint32 b0, uint32 b1) {
    asm volatile(
        "mma.sync.aligned.m16n8k16.row.col.f32.bf16.bf16.f32 "
        "{%0,%1,%2,%3}, {%4,%5,%6,%7}, {%8,%9}, {%0,%1,%2,%3};"
        : "+f"(c[0]), "+f"(c[1]), "+f"(c[2]), "+f"(c[3])
        : "r"(a[0]), "r"(a[1]), "r"(a[2]), "r"(a[3]), "r"(b0), "r"(b1));
}
__device__ __forceinline__ void ldmx4(uint32* r, uint32 addr) {
    asm volatile("ldmatrix.sync.aligned.m8n8.x4.shared.b16 {%0,%1,%2,%3}, [%4];"
                 : "=r"(r[0]), "=r"(r[1]), "=r"(r[2]), "=r"(r[3]) : "r"(addr));
}

// ============================================================================
// N256 split-bf16 GEMM: BM=128, BN=256, BK=32, 3-stage cp.async, 8 warps as
// 2(M)x4(N), warp tile 64x64. 3 mma passes.
// ============================================================================
template<int OUTMODE, int ACT, int SOFTMAX>
__global__ __launch_bounds__(256, 1) void gemm_n256(
    const __nv_bfloat16* __restrict__ Ahi, const __nv_bfloat16* __restrict__ Alo,
    const uint32* __restrict__ Bhi, const uint32* __restrict__ Blo,
    const float* __restrict__ bias,
    float* __restrict__ C, __nv_bfloat16* __restrict__ Chi, __nv_bfloat16* __restrict__ Clo,
    int Mrows, int K, int lda, long sA, long sC)
{
    constexpr int NREAL = 256;
    constexpr int ASTR = 40;
    constexpr int APLW = 128 * ASTR / 2;
    constexpr int AW   = 6 * APLW;
    constexpr int BSTR = 264;
    constexpr int BPL  = 16 * BSTR;
    extern __shared__ __align__(16) uint32 sm[];
    __shared__ float red[128][4];

    const int tid   = threadIdx.x;
    const int wid   = tid >> 5, lane = tid & 31;
    const int warpM = wid >> 2, warpN = wid & 3;
    const int g     = lane >> 2, t = lane & 3;
    const int m0    = blockIdx.x * 128;
    const __nv_bfloat16* Ah = Ahi + (long)blockIdx.z * sA;
    const __nv_bfloat16* Al = Alo + (long)blockIdx.z * sA;

    uint32 smbase;
    asm("{ .reg .u64 tmp; cvta.to.shared.u64 tmp, %1; cvt.u32.u64 %0, tmp; }"
        : "=r"(smbase) : "l"(sm));

    float acc[4][8][4];
#pragma unroll
    for (int i = 0; i < 4; i++)
#pragma unroll
        for (int j = 0; j < 8; j++)
#pragma unroll
            for (int k = 0; k < 4; k++) acc[i][j][k] = 0.f;

    const int nk = K / 32;

    auto fill = [&](int kt) {
        const int st = kt % 3;
        const int k0 = kt * 32;
#pragma unroll
        for (int m = 0; m < 2; m++) {
            const __nv_bfloat16* Asrc = m ? Al : Ah;
#pragma unroll
            for (int j = 0; j < 2; j++) {
                int c = tid + j * 256;
                int r = c >> 2, q = c & 3;
                int gm = m0 + r;
                uint32 d = smbase + ((st * 2 + m) * APLW + r * 20 + q * 4) * 4;
                cp16(d, Asrc + (long)gm * lda + k0 + q * 8, gm < Mrows);
            }
        }
#pragma unroll
        for (int m = 0; m < 2; m++) {
            const uint32* Bsrc = m ? Blo : Bhi;
#pragma unroll
            for (int j = 0; j < 4; j++) {
                int c = tid + j * 256;
                int p = c >> 6, q = c & 63;
                uint32 d = smbase + (AW + (st * 2 + m) * BPL + p * BSTR + q * 4) * 4;
                cp16(d, Bsrc + (long)(k0 / 2 + p) * NREAL + q * 4, true);
            }
        }
        cpcommit();
    };

    fill(0);
    fill(1);
    for (int kt = 0; kt < nk; kt++) {
        if (kt + 2 < nk) { fill(kt + 2); cpwait<2>(); }
        else if (kt + 1 < nk) { cpwait<1>(); }
        else { cpwait<0>(); }
        __syncthreads();
        const int st = kt % 3;
        const uint32 aBaseH = smbase + ((st * 2 + 0) * APLW) * 4;
        const uint32 aBaseL = smbase + ((st * 2 + 1) * APLW) * 4;
        const uint32* B_h = sm + AW + (st * 2 + 0) * BPL;
        const uint32* B_l = sm + AW + (st * 2 + 1) * BPL;
        const int arow = warpM * 64 + (lane & 15);
        const int acol = (lane >> 4) * 8;
#pragma unroll
        for (int ks = 0; ks < 2; ks++) {
            uint32 ah[4][4], al[4][4];
            const int khalf = ks * 16 + acol;
#pragma unroll
            for (int mt = 0; mt < 4; mt++) {
                uint32 off = ((arow + mt * 16) * ASTR + khalf) * 2;
                ldmx4(ah[mt], aBaseH + off);
                ldmx4(al[mt], aBaseL + off);
            }
            const int w0 = ks * 8 + t;
#pragma unroll
            for (int nt = 0; nt < 8; nt++) {
                int nn = warpN * 64 + nt * 8 + g;
                uint32 bh0 = B_h[w0 * BSTR + nn], bh1 = B_h[(w0 + 4) * BSTR + nn];
                uint32 bl0 = B_l[w0 * BSTR + nn], bl1 = B_l[(w0 + 4) * BSTR + nn];
#pragma unroll
                for (int mt = 0; mt < 4; mt++) {
                    mma_bf16(acc[mt][nt], ah[mt], bh0, bh1);
                    mma_bf16(acc[mt][nt], ah[mt], bl0, bl1);
                    mma_bf16(acc[mt][nt], al[mt], bh0, bh1);
                }
            }
        }
        __syncthreads();
    }

    // ---- epilogue ----
    const long cb = (long)blockIdx.z * sC;

#pragma unroll
    for (int mt = 0; mt < 4; mt++)
#pragma unroll
        for (int nt = 0; nt < 8; nt++) {
            int gcol = warpN * 64 + nt * 8 + 2 * t;
            float bb0 = bias[gcol], bb1 = bias[gcol + 1];
            acc[mt][nt][0] += bb0; acc[mt][nt][1] += bb1;
            acc[mt][nt][2] += bb0; acc[mt][nt][3] += bb1;
            if (ACT) {
#pragma unroll
                for (int q = 0; q < 4; q++) acc[mt][nt][q] = fmaxf(acc[mt][nt][q], 0.f);
            }
        }

    if (SOFTMAX) {
        float rmax[4][2], rsum[4][2];
#pragma unroll
        for (int mt = 0; mt < 4; mt++)
#pragma unroll
            for (int h = 0; h < 2; h++) {
                float m = -1e30f;
#pragma unroll
                for (int nt = 0; nt < 8; nt++)
                    m = fmaxf(m, fmaxf(acc[mt][nt][2 * h], acc[mt][nt][2 * h + 1]));
                m = fmaxf(m, __shfl_xor_sync(0xffffffffu, m, 1));
                m = fmaxf(m, __shfl_xor_sync(0xffffffffu, m, 2));
                rmax[mt][h] = m;
            }
        if (t == 0)
#pragma unroll
            for (int mt = 0; mt < 4; mt++)
#pragma unroll
                for (int h = 0; h < 2; h++)
                    red[warpM * 64 + mt * 16 + g + h * 8][warpN] = rmax[mt][h];
        __syncthreads();
#pragma unroll
        for (int mt = 0; mt < 4; mt++)
#pragma unroll
            for (int h = 0; h < 2; h++) {
                int r = warpM * 64 + mt * 16 + g + h * 8;
                rmax[mt][h] = fmaxf(fmaxf(red[r][0], red[r][1]),
                                    fmaxf(red[r][2], red[r][3]));
            }
        __syncthreads();
#pragma unroll
        for (int mt = 0; mt < 4; mt++)
#pragma unroll
            for (int h = 0; h < 2; h++) {
                float s = 0.f;
#pragma unroll
                for (int nt = 0; nt < 8; nt++) {
                    float e0 = __expf(acc[mt][nt][2 * h]     - rmax[mt][h]);
                    float e1 = __expf(acc[mt][nt][2 * h + 1] - rmax[mt][h]);
                    acc[mt][nt][2 * h] = e0; acc[mt][nt][2 * h + 1] = e1;
                    s += e0 + e1;
                }
                s += __shfl_xor_sync(0xffffffffu, s, 1);
                s += __shfl_xor_sync(0xffffffffu, s, 2);
                rsum[mt][h] = s;
            }
        if (t == 0)
#pragma unroll
            for (int mt = 0; mt < 4; mt++)
#pragma unroll
                for (int h = 0; h < 2; h++)
                    red[warpM * 64 + mt * 16 + g + h * 8][warpN] = rsum[mt][h];
        __syncthreads();
#pragma unroll
        for (int mt = 0; mt < 4; mt++)
#pragma unroll
            for (int h = 0; h < 2; h++) {
                int r = warpM * 64 + mt * 16 + g + h * 8;
                float s = red[r][0] + red[r][1] + red[r][2] + red[r][3];
                float inv = 1.f / s;
#pragma unroll
                for (int nt = 0; nt < 8; nt++) {
                    acc[mt][nt][2 * h]     *= inv;
                    acc[mt][nt][2 * h + 1] *= inv;
                }
            }
    }

#pragma unroll
    for (int mt = 0; mt < 4; mt++) {
        int gm = m0 + warpM * 64 + mt * 16 + g;
#pragma unroll
        for (int nt = 0; nt < 8; nt++) {
            int gcol = warpN * 64 + nt * 8 + 2 * t;
            float v00 = acc[mt][nt][0], v01 = acc[mt][nt][1];
            float v10 = acc[mt][nt][2], v11 = acc[mt][nt][3];
            if (OUTMODE == 0) {
                if (gm < Mrows)
                    *reinterpret_cast<float2*>(&C[cb + (long)gm * NREAL + gcol]) = make_float2(v00, v01);
                if (gm + 8 < Mrows)
                    *reinterpret_cast<float2*>(&C[cb + (long)(gm + 8) * NREAL + gcol]) = make_float2(v10, v11);
            } else {
                if (gm < Mrows) {
                    __nv_bfloat162 h(__float2bfloat16(v00), __float2bfloat16(v01));
                    __nv_bfloat162 l(__float2bfloat16(v00 - __bfloat162float(h.x)),
                                     __float2bfloat16(v01 - __bfloat162float(h.y)));
                    *reinterpret_cast<__nv_bfloat162*>(&Chi[cb + (long)gm * NREAL + gcol]) = h;
                    *reinterpret_cast<__nv_bfloat162*>(&Clo[cb + (long)gm * NREAL + gcol]) = l;
                }
                if (gm + 8 < Mrows) {
                    __nv_bfloat162 h(__float2bfloat16(v10), __float2bfloat16(v11));
                    __nv_bfloat162 l(__float2bfloat16(v10 - __bfloat162float(h.x)),
                                     __float2bfloat16(v11 - __bfloat162float(h.y)));
                    *reinterpret_cast<__nv_bfloat162*>(&Chi[cb + (long)(gm + 8) * NREAL + gcol]) = h;
                    *reinterpret_cast<__nv_bfloat162*>(&Clo[cb + (long)(gm + 8) * NREAL + gcol]) = l;
                }
            }
        }
    }
}

// ============================================================================
// FUSED causal conv GEMM + gated0 -> hA directly.
// ============================================================================
__global__ __launch_bounds__(256, 1) void gemm_causal_gated(
    const __nv_bfloat16* __restrict__ Ahi, const __nv_bfloat16* __restrict__ Alo,
    const uint32* __restrict__ Bhi, const uint32* __restrict__ Blo,
    const float* __restrict__ bias,
    const uint32* __restrict__ Wg0Hi, const uint32* __restrict__ Wg0Lo,
    const float* __restrict__ gb0, const float* __restrict__ fb0,
    const float* __restrict__ sW, const float* __restrict__ sB,
    float* __restrict__ hOut)
{
    constexpr int NREAL = 256;
    constexpr int K     = 512;
    constexpr int LDA   = 256;
    constexpr int ASTR = 40;
    constexpr int APLW = 128 * ASTR / 2;
    constexpr int AW   = 6 * APLW;
    constexpr int BSTR = 264;
    constexpr int BPL  = 16 * BSTR;
    constexpr int YPLW = 128 * 132;
    constexpr int ZB0  = 2 * YPLW;
    constexpr int ZBPL = 16 * 56;
    extern __shared__ __align__(16) uint32 sm[];
    __shared__ float zs[128][49];
    __shared__ float zz[128][25];
    __shared__ float sws[24][24];
    __shared__ float sbs[24];

    const int tid   = threadIdx.x;
    const int wid   = tid >> 5, lane = tid & 31;
    const int warpM = wid >> 2, warpN = wid & 3;
    const int g     = lane >> 2, t = lane & 3;
    const int m0    = blockIdx.x * 127;
    const __nv_bfloat16* Ah = Ahi + (long)blockIdx.z * ((long)T0_ * 256);
    const __nv_bfloat16* Al = Alo + (long)blockIdx.z * ((long)T0_ * 256);

    for (int i = tid; i < 576; i += 256) sws[i / 24][i % 24] = sW[i];
    if (tid < 24) sbs[tid] = sB[tid];

    uint32 smbase;
    asm("{ .reg .u64 tmp; cvta.to.shared.u64 tmp, %1; cvt.u32.u64 %0, tmp; }"
        : "=r"(smbase) : "l"(sm));

    float acc[4][8][4];
#pragma unroll
    for (int i = 0; i < 4; i++)
#pragma unroll
        for (int j = 0; j < 8; j++)
#pragma unroll
            for (int k = 0; k < 4; k++) acc[i][j][k] = 0.f;

    const int nk = K / 32;

    auto fill = [&](int kt) {
        const int st = kt % 3;
        const int k0 = kt * 32;
#pragma unroll
        for (int m = 0; m < 2; m++) {
            const __nv_bfloat16* Asrc = m ? Al : Ah;
#pragma unroll
            for (int j = 0; j < 2; j++) {
                int c = tid + j * 256;
                int r = c >> 2, q = c & 3;
                int gm = m0 + r;
                uint32 d = smbase + ((st * 2 + m) * APLW + r * 20 + q * 4) * 4;
                cp16(d, Asrc + (long)gm * LDA + k0 + q * 8, gm < T1_);
            }
        }
#pragma unroll
        for (int m = 0; m < 2; m++) {
            const uint32* Bsrc = m ? Blo : Bhi;
#pragma unroll
            for (int j = 0; j < 4; j++) {
                int c = tid + j * 256;
                int p = c >> 6, q = c & 63;
                uint32 d = smbase + (AW + (st * 2 + m) * BPL + p * BSTR + q * 4) * 4;
                cp16(d, Bsrc + (long)(k0 / 2 + p) * NREAL + q * 4, true);
            }
        }
        cpcommit();
    };

    fill(0);
    fill(1);
    for (int kt = 0; kt < nk; kt++) {
        if (kt + 2 < nk) { fill(kt + 2); cpwait<2>(); }
        else if (kt + 1 < nk) { cpwait<1>(); }
        else { cpwait<0>(); }
        __syncthreads();
        const int st = kt % 3;
        const uint32 aBaseH = smbase + ((st * 2 + 0) * APLW) * 4;
        const uint32 aBaseL = smbase + ((st * 2 + 1) * APLW) * 4;
        const uint32* B_h = sm + AW + (st * 2 + 0) * BPL;
        const uint32* B_l = sm + AW + (st * 2 + 1) * BPL;
        const int arow = warpM * 64 + (lane & 15);
        const int acol = (lane >> 4) * 8;
#pragma unroll
        for (int ks = 0; ks < 2; ks++) {
            uint32 ah[4][4], al[4][4];
            const int khalf = ks * 16 + acol;
#pragma unroll
            for (int mt = 0; mt < 4; mt++) {
                uint32 off = ((arow + mt * 16) * ASTR + khalf) * 2;
                ldmx4(ah[mt], aBaseH + off);
                ldmx4(al[mt], aBaseL + off);
            }
            const int w0 = ks * 8 + t;
#pragma unroll
            for (int nt = 0; nt < 8; nt++) {
                int nn = warpN * 64 + nt * 8 + g;
                uint32 bh0 = B_h[w0 * BSTR + nn], bh1 = B_h[(w0 + 4) * BSTR + nn];
                uint32 bl0 = B_l[w0 * BSTR + nn], bl1 = B_l[(w0 + 4) * BSTR + nn];
#pragma unroll
                for (int mt = 0; mt < 4; mt++) {
                    mma_bf16(acc[mt][nt], ah[mt], bh0, bh1);
                    mma_bf16(acc[mt][nt], ah[mt], bl0, bl1);
                    mma_bf16(acc[mt][nt], al[mt], bh0, bh1);
                }
            }
        }
        __syncthreads();
    }

    auto fillz = [&](int kt) {
        const int st = kt & 1;
#pragma unroll
        for (int j = 0; j < 2; j++) {
            int c = tid + j * 256;
            if (c < 384) {
                int plane = c / 192, cc = c % 192, p = cc / 12, q = cc % 12;
                const uint32* src = plane ? Wg0Lo : Wg0Hi;
                uint32 d = smbase + (ZB0 + (st * 2 + plane) * ZBPL + p * 56 + q * 4) * 4;
                cp16(d, src + (long)(kt * 16 + p) * 48 + q * 4, true);
            }
        }
        cpcommit();
    };
    fillz(0);

#pragma unroll
    for (int mt = 0; mt < 4; mt++) {
        int r0 = warpM * 64 + mt * 16 + g;
#pragma unroll
        for (int nt = 0; nt < 8; nt++) {
            int c = warpN * 64 + nt * 8 + 2 * t;
            float bb0 = bias[c], bb1 = bias[c + 1];
            float v00 = acc[mt][nt][0] + bb0, v01 = acc[mt][nt][1] + bb1;
            float v10 = acc[mt][nt][2] + bb0, v11 = acc[mt][nt][3] + bb1;
            __nv_bfloat162 h0(__float2bfloat16(v00), __float2bfloat16(v01));
            __nv_bfloat162 l0(__float2bfloat16(v00 - __bfloat162float(h0.x)),
                              __float2bfloat16(v01 - __bfloat162float(h0.y)));
            __nv_bfloat162 h1(__float2bfloat16(v10), __float2bfloat16(v11));
            __nv_bfloat162 l1(__float2bfloat16(v10 - __bfloat162float(h1.x)),
                              __float2bfloat16(v11 - __bfloat162float(h1.y)));
            sm[r0 * 132 + (c >> 1)]              = *reinterpret_cast<uint32*>(&h0);
            sm[YPLW + r0 * 132 + (c >> 1)]       = *reinterpret_cast<uint32*>(&l0);
            sm[(r0 + 8) * 132 + (c >> 1)]        = *reinterpret_cast<uint32*>(&h1);
            sm[YPLW + (r0 + 8) * 132 + (c >> 1)] = *reinterpret_cast<uint32*>(&l1);
        }
    }
    __syncthreads();

    const int zwM = wid >> 1, zwN = wid & 1;
    float zacc[2][3][4];
#pragma unroll
    for (int i = 0; i < 2; i++)
#pragma unroll
        for (int j = 0; j < 3; j++)
#pragma unroll
            for (int k = 0; k < 4; k++) zacc[i][j][k] = 0.f;

    for (int kt = 0; kt < 16; kt++) {
        if (kt + 1 < 16) { fillz(kt + 1); cpwait<1>(); } else { cpwait<0>(); }
        __syncthreads();
        const int st = kt & 1;
        const uint32* Bz_h = sm + ZB0 + (st * 2 + 0) * ZBPL;
        const uint32* Bz_l = sm + ZB0 + (st * 2 + 1) * ZBPL;
        const int colbase = (kt & 7) * 32;
        const int rplus   = (kt >= 8) ? 1 : 0;
#pragma unroll
        for (int ks = 0; ks < 2; ks++) {
            uint32 zah[2][4], zal[2][4];
            const int khalf = colbase + ks * 16 + (lane >> 4) * 8;
#pragma unroll
            for (int mt = 0; mt < 2; mt++) {
                int row = zwM * 32 + mt * 16 + (lane & 15) + rplus;
                row = (row > 127) ? 127 : row;
                uint32 off = (uint32)(row * 264 + khalf) * 2;
                ldmx4(zah[mt], smbase + off);
                ldmx4(zal[mt], smbase + YPLW * 4 + off);
            }
            const int w0 = ks * 8 + t;
#pragma unroll
            for (int nt = 0; nt < 3; nt++) {
                int nn = zwN * 24 + nt * 8 + g;
                uint32 bh0 = Bz_h[w0 * 56 + nn], bh1 = Bz_h[(w0 + 4) * 56 + nn];
                uint32 bl0 = Bz_l[w0 * 56 + nn], bl1 = Bz_l[(w0 + 4) * 56 + nn];
#pragma unroll
                for (int mt = 0; mt < 2; mt++) {
                    mma_bf16(zacc[mt][nt], zah[mt], bh0, bh1);
                    mma_bf16(zacc[mt][nt], zah[mt], bl0, bl1);
                    mma_bf16(zacc[mt][nt], zal[mt], bh0, bh1);
                }
            }
        }
        __syncthreads();
    }

#pragma unroll
    for (int mt = 0; mt < 2; mt++) {
        int r0 = zwM * 32 + mt * 16 + g;
#pragma unroll
        for (int nt = 0; nt < 3; nt++) {
            int col = zwN * 24 + nt * 8 + 2 * t;
            float b0 = (col < 24)     ? gb0[col]     : fb0[col - 24];
            float b1 = (col + 1 < 24) ? gb0[col + 1] : fb0[col + 1 - 24];
            zs[r0][col]         = zacc[mt][nt][0] + b0;
            zs[r0][col + 1]     = zacc[mt][nt][1] + b1;
            zs[r0 + 8][col]     = zacc[mt][nt][2] + b0;
            zs[r0 + 8][col + 1] = zacc[mt][nt][3] + b1;
        }
    }
    __syncthreads();
    if (tid < 128) {
#pragma unroll
        for (int c = 0; c < 24; c++)
            zz[tid][c] = sigmoidf_(zs[tid][c]) * tanhf_(zs[tid][24 + c]);
    }
    __syncthreads();
    {
        int r = tid & 127, half = tid >> 7;
        long gmh = m0 + r;
        if (r < 127 && gmh < T2_) {
            float o[12];
#pragma unroll
            for (int j = 0; j < 12; j++) o[j] = sbs[half * 12 + j];
#pragma unroll
            for (int c = 0; c < 24; c++) {
                float zv = zz[r][c];
#pragma unroll
                for (int j = 0; j < 12; j++) o[j] += zv * sws[c][half * 12 + j];
            }
            float* ob = hOut + ((long)blockIdx.z * T2_ + gmh) * 24 + half * 12;
#pragma unroll
            for (int j = 0; j < 6; j++)
                *reinterpret_cast<float2*>(&ob[2 * j]) = make_float2(o[2 * j], o[2 * j + 1]);
        }
    }
}

// ============================================================================
// fp32 -> hi/lo bf16 split
// ============================================================================
__global__ void split_bf16_vec(const float* __restrict__ s,
                               __nv_bfloat16* __restrict__ hi,
                               __nv_bfloat16* __restrict__ lo, long n)
{
    long i = ((long)blockIdx.x * 256 + threadIdx.x) * 4;
    if (i >= n) return;
    float4 v = *reinterpret_cast<const float4*>(s + i);
    __nv_bfloat16 h0 = __float2bfloat16(v.x), h1 = __float2bfloat16(v.y);
    __nv_bfloat16 h2 = __float2bfloat16(v.z), h3 = __float2bfloat16(v.w);
    __nv_bfloat16 l0 = __float2bfloat16(v.x - __bfloat162float(h0));
    __nv_bfloat16 l1 = __float2bfloat16(v.y - __bfloat162float(h1));
    __nv_bfloat16 l2 = __float2bfloat16(v.z - __bfloat162float(h2));
    __nv_bfloat16 l3 = __float2bfloat16(v.w - __bfloat162float(h3));
    reinterpret_cast<__nv_bfloat162*>(hi + i)[0] = __nv_bfloat162(h0, h1);
    reinterpret_cast<__nv_bfloat162*>(hi + i)[1] = __nv_bfloat162(h2, h3);
    reinterpret_cast<__nv_bfloat162*>(lo + i)[0] = __nv_bfloat162(l0, l1);
    reinterpret_cast<__nv_bfloat162*>(lo + i)[1] = __nv_bfloat162(l2, l3);
}

// ============================================================================
// One-shot weight prep
// ============================================================================
__device__ __forceinline__ void pair_store(float w0, float w1,
                                           uint32* bhi, uint32* blo, int idx)
{
    __nv_bfloat16 h0 = __float2bfloat16(w0), h1 = __float2bfloat16(w1);
    __nv_bfloat16 l0 = __float2bfloat16(w0 - __bfloat162float(h0));
    __nv_bfloat16 l1 = __float2bfloat16(w1 - __bfloat162float(h1));
    __nv_bfloat162 hw(h0, h1), lw(l0, l1);
    bhi[idx] = *reinterpret_cast<uint32*>(&hw);
    blo[idx] = *reinterpret_cast<uint32*>(&lw);
}

__global__ void prep_weights(
    const float* __restrict__ cauW, const float* __restrict__ f1W,
    const float* __restrict__ f2W,
    const float* __restrict__ gW, const float* __restrict__ fW,
    uint32* __restrict__ cauHi, uint32* __restrict__ cauLo,
    uint32* __restrict__ f1Hi,  uint32* __restrict__ f1Lo,
    uint32* __restrict__ f2Hi,  uint32* __restrict__ f2Lo,
    uint32* __restrict__ g0Hi,  uint32* __restrict__ g0Lo)
{
    int bid = blockIdx.x, tid = threadIdx.x;
    if (bid < 256) {
        int idx = bid * 256 + tid;
        int p = idx >> 8, n = idx & 255;
        pair_store(cauW[(2 * p) * 256 + n], cauW[(2 * p + 1) * 256 + n], cauHi, cauLo, idx);
    } else if (bid < 320) {
        int idx = (bid - 256) * 256 + tid;
        int p = idx >> 8, n = idx & 255;
        pair_store(f1W[(2 * p) * 256 + n], f1W[(2 * p + 1) * 256 + n], f1Hi, f1Lo, idx);
    } else if (bid < 448) {
        int idx = (bid - 320) * 256 + tid;
        int p = idx >> 8, n = idx & 255;
        pair_store(f2W[(2 * p) * 256 + n], f2W[(2 * p + 1) * 256 + n], f2Hi, f2Lo, idx);
    } else {
        int idx = (bid - 448) * 256 + tid;
        if (idx < 256 * 48) {
            int p = idx / 48, n = idx % 48;
            const float* src = (n < 24) ? gW : fW;
            int nn = (n < 24) ? n : n - 24;
            pair_store(src[(2 * p) * 24 + nn], src[(2 * p + 1) * 24 + nn], g0Hi, g0Lo, idx);
        }
    }
}

// ============================================================================
// Fused dilated gated layer (24 ch, f32x2) — weight-reuse version.
// __launch_bounds__(256, 3): force regs <= 85 so 3 CTAs fit per SM
// (R10/R11 sat at 2 CTAs/SM = 21% occ; latency-bound). Spill candidates are
// zv[2][12] held across the barrier — cold path, acceptable.
// ============================================================================
#define DGT 256
__global__ __launch_bounds__(256, 3) void dilated_gated(
    const float* __restrict__ hin, float* __restrict__ hout,
    const float* __restrict__ gateW, const float* __restrict__ gateB,
    const float* __restrict__ filtW, const float* __restrict__ filtB,
    const float* __restrict__ scaleW, const float* __restrict__ scaleB,
    int layer, int Tin, int Tout, int d)
{
    extern __shared__ __align__(16) float smf[];
    float* xs0 = smf;                 // [256][25]
    float* xs1 = smf + DGT * 25;      // [256][25]
    ULL*   wb  = reinterpret_cast<ULL*>(smf + 2 * DGT * 25);
    ULL* gp0W = wb;            // [24*12]
    ULL* gp1W = wb + 288;
    ULL* fp0W = wb + 576;
    ULL* fp1W = wb + 864;
    ULL* spW  = wb + 1152;
    ULL* gb2W = wb + 1440;     // [12]
    ULL* fb2W = wb + 1452;
    ULL* sb2W = wb + 1464;
    float* zzW = smf;          // aliases xs0/xs1 after conv (stride 25)

    const int tid = threadIdx.x;
    const int b   = blockIdx.y;
    const int t0  = blockIdx.x * DGT;
    const int wbase = layer * 1152;
    for (int i = tid; i < 288; i += 256) {
        int c = i / 12, p = i % 12, o = 2 * p;
        gp0W[i] = pk2(gateW[wbase + c * 24 + o],       gateW[wbase + c * 24 + o + 1]);
        gp1W[i] = pk2(gateW[wbase + 576 + c * 24 + o], gateW[wbase + 576 + c * 24 + o + 1]);
        fp0W[i] = pk2(filtW[wbase + c * 24 + o],       filtW[wbase + c * 24 + o + 1]);
        fp1W[i] = pk2(filtW[wbase + 576 + c * 24 + o], filtW[wbase + 576 + c * 24 + o + 1]);
        spW[i]  = pk2(scaleW[layer * 576 + c * 24 + o], scaleW[layer * 576 + c * 24 + o + 1]);
    }
    if (tid < 12) {
        gb2W[tid] = pk2(gateB[layer * 24 + 2 * tid], gateB[layer * 24 + 2 * tid + 1]);
        fb2W[tid] = pk2(filtB[layer * 24 + 2 * tid], filtB[layer * 24 + 2 * tid + 1]);
        sb2W[tid] = pk2(scaleB[layer * 24 + 2 * tid], scaleB[layer * 24 + 2 * tid + 1]);
    }
    const float* hb = hin + (long)b * Tin * 24;
    for (int i = tid; i < DGT * 24; i += 256) {
        int r = i / 24, c = i % 24;
        int ta = t0 + r, tc = t0 + d + r;
        xs0[r * 25 + c] = (ta < Tin) ? hb[(long)ta * 24 + c] : 0.f;
        xs1[r * 25 + c] = (tc < Tin) ? hb[(long)tc * 24 + c] : 0.f;
    }
    __syncthreads();

    const int r    = tid & 127;
    const int half = tid >> 7;
    ULL gA[2][6], fA[2][6];
#pragma unroll
    for (int p = 0; p < 6; p++) {
        ULL gb = gb2W[half * 6 + p], fb = fb2W[half * 6 + p];
        gA[0][p] = gb; gA[1][p] = gb;
        fA[0][p] = fb; fA[1][p] = fb;
    }
#pragma unroll
    for (int c = 0; c < 24; c++) {
        ULL xa0 = dup2(xs0[r * 25 + c]);
        ULL xa1 = dup2(xs1[r * 25 + c]);
        ULL xb0 = dup2(xs0[(r + 128) * 25 + c]);
        ULL xb1 = dup2(xs1[(r + 128) * 25 + c]);
#pragma unroll
        for (int p = 0; p < 6; p++) {
            int pp = c * 12 + half * 6 + p;
            ULL g0 = gp0W[pp], g1 = gp1W[pp], f0 = fp0W[pp], f1 = fp1W[pp];
            ffma2(gA[0][p], xa0, g0); ffma2(gA[0][p], xa1, g1);
            ffma2(fA[0][p], xa0, f0); ffma2(fA[0][p], xa1, f1);
            ffma2(gA[1][p], xb0, g0); ffma2(gA[1][p], xb1, g1);
            ffma2(fA[1][p], xb0, f0); ffma2(fA[1][p], xb1, f1);
        }
    }
    // activations to registers
    float zv[2][12];
#pragma unroll
    for (int ts = 0; ts < 2; ts++)
#pragma unroll
        for (int p = 0; p < 6; p++) {
            float2 gv = unpk2(gA[ts][p]);
            float2 fv = unpk2(fA[ts][p]);
            zv[ts][2 * p]     = gatedact_(gv.x, fv.x);
            zv[ts][2 * p + 1] = gatedact_(gv.y, fv.y);
        }
    __syncthreads();   // xs reads done everywhere -> safe to overwrite with zz
#pragma unroll
    for (int ts = 0; ts < 2; ts++) {
        int row = r + 128 * ts;
#pragma unroll
        for (int j = 0; j < 12; j++)
            zzW[row * 25 + half * 12 + j] = zv[ts][j];
    }
    __syncthreads();

    // 1x1: thread handles timestep t0 + tid
    int t = t0 + tid;
    if (t >= Tout) return;
    ULL o2[12];
#pragma unroll
    for (int p = 0; p < 12; p++) o2[p] = sb2W[p];
#pragma unroll
    for (int c = 0; c < 24; c++) {
        ULL zd = dup2(zzW[tid * 25 + c]);
#pragma unroll
        for (int p = 0; p < 12; p++) ffma2(o2[p], zd, spW[c * 12 + p]);
    }
    ULL* ob = reinterpret_cast<ULL*>(hout + ((long)b * Tout + t) * 24);
#pragma unroll
    for (int p = 0; p < 12; p++) ob[p] = o2[p];
}

// ============================================================================
// Final residual add + res conv (24->128) + relu -> a0 as bf16 hi/lo split
// ============================================================================
__global__ __launch_bounds__(128) void resconv_relu(
    const float* __restrict__ prev8, const float* __restrict__ out8,
    const float* __restrict__ resW, const float* __restrict__ resB,
    __nv_bfloat16* __restrict__ a0hi, __nv_bfloat16* __restrict__ a0lo)
{
    __shared__ float ss[32][25];
    __shared__ float Ws[24][128];
    __shared__ float bs[128];
    const int tid = threadIdx.x;
    const int b   = blockIdx.y;
    const int t0  = blockIdx.x * 32;
    for (int i = tid; i < 24 * 128; i += 128) Ws[i / 128][i % 128] = resW[8 * 24 * 128 + i];
    bs[tid] = resB[8 * 128 + tid];
    const float* pb = prev8 + ((long)b * 15872 + 256) * 24;
    const float* ob = out8  + (long)b * TFIN * 24;
    for (int i = tid; i < 32 * 24; i += 128) {
        int r = i / 24, c = i % 24;
        long t = t0 + r;
        ss[r][c] = pb[t * 24 + c] + ob[t * 24 + c];
    }
    __syncthreads();
    long obase = ((long)b * TFIN + t0) * 128;
#pragma unroll 4
    for (int r = 0; r < 32; r++) {
        float a = bs[tid];
#pragma unroll
        for (int c = 0; c < 24; c++) a += ss[r][c] * Ws[c][tid];
        a = fmaxf(a, 0.f);
        __nv_bfloat16 h = __float2bfloat16(a);
        __nv_bfloat16 l = __float2bfloat16(a - __bfloat162float(h));
        a0hi[obase + (long)r * 128 + tid] = h;
        a0lo[obase + (long)r * 128 + tid] = l;
    }
}

// ============================================================================
extern "C" void kernel_launch(void* const* d_in, const int* in_sizes, int n_in,
                              void* d_out, int out_size)
{
    const float* x        = (const float*)d_in[0];
    const float* causal_W = (const float*)d_in[1];
    const float* causal_b = (const float*)d_in[2];
    const float* gW0      = (const float*)d_in[3];
    const float* gb0      = (const float*)d_in[4];
    const float* fW0      = (const float*)d_in[5];
    const float* fb0      = (const float*)d_in[6];
    const float* sW0      = (const float*)d_in[7];
    const float* sb0      = (const float*)d_in[8];
    const float* gateW    = (const float*)d_in[9];
    const float* gateB    = (const float*)d_in[10];
    const float* filtW    = (const float*)d_in[11];
    const float* filtB    = (const float*)d_in[12];
    const float* scaleW   = (const float*)d_in[13];
    const float* scaleB   = (const float*)d_in[14];
    const float* resW     = (const float*)d_in[15];
    const float* resB     = (const float*)d_in[16];
    const float* f1W      = (const float*)d_in[17];
    const float* f1b      = (const float*)d_in[18];
    const float* f2W      = (const float*)d_in[19];
    const float* f2b      = (const float*)d_in[20];
    float* out = (float*)d_out;

    __nv_bfloat16 *xhi, *xlo, *a0hi, *a0lo, *a1hi, *a1lo;
    float *hA, *hB;
    uint32 *WcauHi, *WcauLo, *Wg0Hi, *Wg0Lo, *Wf1Hi, *Wf1Lo, *Wf2Hi, *Wf2Lo;
    cudaGetSymbolAddress((void**)&xhi,  g_xhi);  cudaGetSymbolAddress((void**)&xlo,  g_xlo);
    cudaGetSymbolAddress((void**)&hA,   g_hA);   cudaGetSymbolAddress((void**)&hB,   g_hB);
    cudaGetSymbolAddress((void**)&a0hi, g_a0hi); cudaGetSymbolAddress((void**)&a0lo, g_a0lo);
    cudaGetSymbolAddress((void**)&a1hi, g_a1hi); cudaGetSymbolAddress((void**)&a1lo, g_a1lo);
    cudaGetSymbolAddress((void**)&WcauHi, g_WcauHi); cudaGetSymbolAddress((void**)&WcauLo, g_WcauLo);
    cudaGetSymbolAddress((void**)&Wg0Hi,  g_Wg0Hi);  cudaGetSymbolAddress((void**)&Wg0Lo,  g_Wg0Lo);
    cudaGetSymbolAddress((void**)&Wf1Hi,  g_Wf1Hi);  cudaGetSymbolAddress((void**)&Wf1Lo,  g_Wf1Lo);
    cudaGetSymbolAddress((void**)&Wf2Hi,  g_Wf2Hi);  cudaGetSymbolAddress((void**)&Wf2Lo,  g_Wf2Lo);

    const int SMEM_N256 = (6 * 2560 + 6 * 16 * 264) * 4;    // 162816 B
    const int SMEM_DG   = (2 * 256 * 25 + 2 * 1476) * 4;    // 63008 B
    cudaFuncSetAttribute((const void*)gemm_n256<1,1,0>, cudaFuncAttributeMaxDynamicSharedMemorySize, SMEM_N256);
    cudaFuncSetAttribute((const void*)gemm_n256<0,0,1>, cudaFuncAttributeMaxDynamicSharedMemorySize, SMEM_N256);
    cudaFuncSetAttribute((const void*)gemm_causal_gated, cudaFuncAttributeMaxDynamicSharedMemorySize, SMEM_N256);
    cudaFuncSetAttribute((const void*)dilated_gated, cudaFuncAttributeMaxDynamicSharedMemorySize, SMEM_DG);

    // 0. preprocessing
    long nx = (long)B_ * T0_ * 256;
    split_bf16_vec<<<(int)(nx / 4 / 256), 256>>>(x, xhi, xlo, nx);               // 1
    prep_weights<<<496, 256>>>(causal_W, f1W, f2W, gW0, fW0,
                               WcauHi, WcauLo, Wf1Hi, Wf1Lo,
                               Wf2Hi, Wf2Lo, Wg0Hi, Wg0Lo);                      // 2

    // 1. FUSED causal conv + gated0 -> hA                                     // 3
    gemm_causal_gated<<<dim3(129, 1, B_), 256, SMEM_N256>>>(
        xhi, xlo, WcauHi, WcauLo, causal_b,
        Wg0Hi, Wg0Lo, gb0, fb0, sW0, sb0, hA);

    // 2. nine dilated gated layers (ping-pong hA/hB)                          // 4..12
    int Tin = T2_;
    float* hin  = hA;
    float* hnew = hB;
    for (int i = 0; i < 9; i++) {
        int d = 2 << i;
        int Tout = Tin - d;
        dim3 g((Tout + DGT - 1) / DGT, B_);
        dilated_gated<<<g, 256, SMEM_DG>>>(hin, hnew, gateW, gateB, filtW, filtB,
                                           scaleW, scaleB, i, Tin, Tout, d);
        float* tmp = hin; hin = hnew; hnew = tmp;
        Tin = Tout;
    }
    // hin = layer-8 output (T=15360), hnew = layer-7 output (T=15872)

    // 3. residual add + res conv + relu -> a0 hi/lo
    resconv_relu<<<dim3(480, B_), 128>>>(hnew, hin, resW, resB, a0hi, a0lo);

    // 4. f1 + relu -> a1 hi/lo
    gemm_n256<1,1,0><<<dim3(960, 1, 1), 256, SMEM_N256>>>(
        a0hi, a0lo, Wf1Hi, Wf1Lo, f1b, nullptr, a1hi, a1lo,
        B_ * TFIN, 128, 128, 0, 0);

    // 5. f2 + fused exact softmax -> probabilities fp32 in d_out
    gemm_n256<0,0,1><<<dim3(960, 1, 1), 256, SMEM_N256>>>(
        a1hi, a1lo, Wf2Hi, Wf2Lo, f2b, out, nullptr, nullptr,
        B_ * TFIN, 256, 256, 0, 0);
}

// round 16
// speedup vs baseline: 1.0159x; 1.0159x over previous
#include <cuda_runtime.h>
#include <cuda_bf16.h>

#define B_   8
#define T0_  16384
#define T1_  16383
#define T2_  16382
#define TFIN 15360

typedef unsigned long long ULL;
typedef unsigned int uint32;

// -------- scratch (device globals; no allocation allowed) --------
__device__ __nv_bfloat16 g_xhi [(size_t)B_ * T0_ * 256];
__device__ __nv_bfloat16 g_xlo [(size_t)B_ * T0_ * 256];
__device__ float g_hA [(size_t)B_ * T2_ * 24];
__device__ float g_hB [(size_t)B_ * T2_ * 24];
__device__ __nv_bfloat16 g_a0hi[(size_t)B_ * TFIN * 128];
__device__ __nv_bfloat16 g_a0lo[(size_t)B_ * TFIN * 128];
// weights in k-paired bf16x2 word layout [K/2][N]
__device__ uint32 g_WcauHi[256 * 256], g_WcauLo[256 * 256];
__device__ uint32 g_Wg0Hi [256 * 48],  g_Wg0Lo [256 * 48];
__device__ uint32 g_Wf1Hi [64 * 256],  g_Wf1Lo [64 * 256];
__device__ uint32 g_Wf2Hi [128 * 256], g_Wf2Lo [128 * 256];

// -------- small helpers --------
__device__ __forceinline__ float sigmoidf_(float x) { return 1.f / (1.f + __expf(-x)); }
__device__ __forceinline__ float tanhf_(float x) {
    float e = __expf(2.f * x);
    return 1.f - 2.f / (e + 1.f);
}
__device__ __forceinline__ float gatedact_(float g, float f) {
    g = fminf(fmaxf(g, -30.f), 30.f);
    f = fminf(fmaxf(f, -15.f), 15.f);
    float a = __expf(-g);
    float b = __expf(2.f * f);
    return __fdividef(b - 1.f, (1.f + a) * (b + 1.f));
}
__device__ __forceinline__ ULL pk2(float lo, float hi) {
    ULL r; asm("mov.b64 %0, {%1, %2};" : "=l"(r) : "f"(lo), "f"(hi)); return r;
}
__device__ __forceinline__ ULL dup2(float x) {
    ULL r; asm("mov.b64 %0, {%1, %1};" : "=l"(r) : "f"(x)); return r;
}
__device__ __forceinline__ float2 unpk2(ULL v) {
    float2 f; asm("mov.b64 {%0, %1}, %2;" : "=f"(f.x), "=f"(f.y) : "l"(v)); return f;
}
__device__ __forceinline__ void ffma2(ULL& d, ULL a, ULL b) {
    asm("fma.rn.f32x2 %0, %1, %2, %0;" : "+l"(d) : "l"(a), "l"(b));
}

// -------- cp.async --------
__device__ __forceinline__ void cp16(uint32 dst, const void* src, bool pred) {
    int sz = pred ? 16 : 0;
    asm volatile("cp.async.ca.shared.global [%0], [%1], 16, %2;"
                 :: "r"(dst), "l"(src), "r"(sz));
}
__device__ __forceinline__ void cpcommit() { asm volatile("cp.async.commit_group;"); }
template<int N> __device__ __forceinline__ void cpwait() {
    asm volatile("cp.async.wait_group %0;" :: "n"(N));
}

// -------- bf16 mma + ldmatrix --------
__device__ __forceinline__ void mma_bf16(float* c, const uint32* a, uint32 b0, uint32 b1) {
    asm volatile(
        "mma.sync.aligned.m16n8k16.row.col.f32.bf16.bf16.f32 "
        "{%0,%1,%2,%3}, {%4,%5,%6,%7}, {%8,%9}, {%0,%1,%2,%3};"
        : "+f"(c[0]), "+f"(c[1]), "+f"(c[2]), "+f"(c[3])
        : "r"(a[0]), "r"(a[1]), "r"(a[2]), "r"(a[3]), "r"(b0), "r"(b1));
}
__device__ __forceinline__ void ldmx4(uint32* r, uint32 addr) {
    asm volatile("ldmatrix.sync.aligned.m8n8.x4.shared.b16 {%0,%1,%2,%3}, [%4];"
                 : "=r"(r[0]), "=r"(r[1]), "=r"(r[2]), "=r"(r[3]) : "r"(addr));
}

// ============================================================================
// FUSED causal conv GEMM + gated0 -> hA directly (validated R10 kernel).
// ============================================================================
__global__ __launch_bounds__(256, 1) void gemm_causal_gated(
    const __nv_bfloat16* __restrict__ Ahi, const __nv_bfloat16* __restrict__ Alo,
    const uint32* __restrict__ Bhi, const uint32* __restrict__ Blo,
    const float* __restrict__ bias,
    const uint32* __restrict__ Wg0Hi, const uint32* __restrict__ Wg0Lo,
    const float* __restrict__ gb0, const float* __restrict__ fb0,
    const float* __restrict__ sW, const float* __restrict__ sB,
    float* __restrict__ hOut)
{
    constexpr int NREAL = 256;
    constexpr int K     = 512;
    constexpr int LDA   = 256;
    constexpr int ASTR = 40;
    constexpr int APLW = 128 * ASTR / 2;
    constexpr int AW   = 6 * APLW;
    constexpr int BSTR = 264;
    constexpr int BPL  = 16 * BSTR;
    constexpr int YPLW = 128 * 132;
    constexpr int ZB0  = 2 * YPLW;
    constexpr int ZBPL = 16 * 56;
    extern __shared__ __align__(16) uint32 sm[];
    __shared__ float zs[128][49];
    __shared__ float zz[128][25];
    __shared__ float sws[24][24];
    __shared__ float sbs[24];

    const int tid   = threadIdx.x;
    const int wid   = tid >> 5, lane = tid & 31;
    const int warpM = wid >> 2, warpN = wid & 3;
    const int g     = lane >> 2, t = lane & 3;
    const int m0    = blockIdx.x * 127;
    const __nv_bfloat16* Ah = Ahi + (long)blockIdx.z * ((long)T0_ * 256);
    const __nv_bfloat16* Al = Alo + (long)blockIdx.z * ((long)T0_ * 256);

    for (int i = tid; i < 576; i += 256) sws[i / 24][i % 24] = sW[i];
    if (tid < 24) sbs[tid] = sB[tid];

    uint32 smbase;
    asm("{ .reg .u64 tmp; cvta.to.shared.u64 tmp, %1; cvt.u32.u64 %0, tmp; }"
        : "=r"(smbase) : "l"(sm));

    float acc[4][8][4];
#pragma unroll
    for (int i = 0; i < 4; i++)
#pragma unroll
        for (int j = 0; j < 8; j++)
#pragma unroll
            for (int k = 0; k < 4; k++) acc[i][j][k] = 0.f;

    const int nk = K / 32;

    auto fill = [&](int kt) {
        const int st = kt % 3;
        const int k0 = kt * 32;
#pragma unroll
        for (int m = 0; m < 2; m++) {
            const __nv_bfloat16* Asrc = m ? Al : Ah;
#pragma unroll
            for (int j = 0; j < 2; j++) {
                int c = tid + j * 256;
                int r = c >> 2, q = c & 3;
                int gm = m0 + r;
                uint32 d = smbase + ((st * 2 + m) * APLW + r * 20 + q * 4) * 4;
                cp16(d, Asrc + (long)gm * LDA + k0 + q * 8, gm < T1_);
            }
        }
#pragma unroll
        for (int m = 0; m < 2; m++) {
            const uint32* Bsrc = m ? Blo : Bhi;
#pragma unroll
            for (int j = 0; j < 4; j++) {
                int c = tid + j * 256;
                int p = c >> 6, q = c & 63;
                uint32 d = smbase + (AW + (st * 2 + m) * BPL + p * BSTR + q * 4) * 4;
                cp16(d, Bsrc + (long)(k0 / 2 + p) * NREAL + q * 4, true);
            }
        }
        cpcommit();
    };

    fill(0);
    fill(1);
    for (int kt = 0; kt < nk; kt++) {
        if (kt + 2 < nk) { fill(kt + 2); cpwait<2>(); }
        else if (kt + 1 < nk) { cpwait<1>(); }
        else { cpwait<0>(); }
        __syncthreads();
        const int st = kt % 3;
        const uint32 aBaseH = smbase + ((st * 2 + 0) * APLW) * 4;
        const uint32 aBaseL = smbase + ((st * 2 + 1) * APLW) * 4;
        const uint32* B_h = sm + AW + (st * 2 + 0) * BPL;
        const uint32* B_l = sm + AW + (st * 2 + 1) * BPL;
        const int arow = warpM * 64 + (lane & 15);
        const int acol = (lane >> 4) * 8;
#pragma unroll
        for (int ks = 0; ks < 2; ks++) {
            uint32 ah[4][4], al[4][4];
            const int khalf = ks * 16 + acol;
#pragma unroll
            for (int mt = 0; mt < 4; mt++) {
                uint32 off = ((arow + mt * 16) * ASTR + khalf) * 2;
                ldmx4(ah[mt], aBaseH + off);
                ldmx4(al[mt], aBaseL + off);
            }
            const int w0 = ks * 8 + t;
#pragma unroll
            for (int nt = 0; nt < 8; nt++) {
                int nn = warpN * 64 + nt * 8 + g;
                uint32 bh0 = B_h[w0 * BSTR + nn], bh1 = B_h[(w0 + 4) * BSTR + nn];
                uint32 bl0 = B_l[w0 * BSTR + nn], bl1 = B_l[(w0 + 4) * BSTR + nn];
#pragma unroll
                for (int mt = 0; mt < 4; mt++) {
                    mma_bf16(acc[mt][nt], ah[mt], bh0, bh1);
                    mma_bf16(acc[mt][nt], ah[mt], bl0, bl1);
                    mma_bf16(acc[mt][nt], al[mt], bh0, bh1);
                }
            }
        }
        __syncthreads();
    }

    auto fillz = [&](int kt) {
        const int st = kt & 1;
#pragma unroll
        for (int j = 0; j < 2; j++) {
            int c = tid + j * 256;
            if (c < 384) {
                int plane = c / 192, cc = c % 192, p = cc / 12, q = cc % 12;
                const uint32* src = plane ? Wg0Lo : Wg0Hi;
                uint32 d = smbase + (ZB0 + (st * 2 + plane) * ZBPL + p * 56 + q * 4) * 4;
                cp16(d, src + (long)(kt * 16 + p) * 48 + q * 4, true);
            }
        }
        cpcommit();
    };
    fillz(0);

#pragma unroll
    for (int mt = 0; mt < 4; mt++) {
        int r0 = warpM * 64 + mt * 16 + g;
#pragma unroll
        for (int nt = 0; nt < 8; nt++) {
            int c = warpN * 64 + nt * 8 + 2 * t;
            float bb0 = bias[c], bb1 = bias[c + 1];
            float v00 = acc[mt][nt][0] + bb0, v01 = acc[mt][nt][1] + bb1;
            float v10 = acc[mt][nt][2] + bb0, v11 = acc[mt][nt][3] + bb1;
            __nv_bfloat162 h0(__float2bfloat16(v00), __float2bfloat16(v01));
            __nv_bfloat162 l0(__float2bfloat16(v00 - __bfloat162float(h0.x)),
                              __float2bfloat16(v01 - __bfloat162float(h0.y)));
            __nv_bfloat162 h1(__float2bfloat16(v10), __float2bfloat16(v11));
            __nv_bfloat162 l1(__float2bfloat16(v10 - __bfloat162float(h1.x)),
                              __float2bfloat16(v11 - __bfloat162float(h1.y)));
            sm[r0 * 132 + (c >> 1)]              = *reinterpret_cast<uint32*>(&h0);
            sm[YPLW + r0 * 132 + (c >> 1)]       = *reinterpret_cast<uint32*>(&l0);
            sm[(r0 + 8) * 132 + (c >> 1)]        = *reinterpret_cast<uint32*>(&h1);
            sm[YPLW + (r0 + 8) * 132 + (c >> 1)] = *reinterpret_cast<uint32*>(&l1);
        }
    }
    __syncthreads();

    const int zwM = wid >> 1, zwN = wid & 1;
    float zacc[2][3][4];
#pragma unroll
    for (int i = 0; i < 2; i++)
#pragma unroll
        for (int j = 0; j < 3; j++)
#pragma unroll
            for (int k = 0; k < 4; k++) zacc[i][j][k] = 0.f;

    for (int kt = 0; kt < 16; kt++) {
        if (kt + 1 < 16) { fillz(kt + 1); cpwait<1>(); } else { cpwait<0>(); }
        __syncthreads();
        const int st = kt & 1;
        const uint32* Bz_h = sm + ZB0 + (st * 2 + 0) * ZBPL;
        const uint32* Bz_l = sm + ZB0 + (st * 2 + 1) * ZBPL;
        const int colbase = (kt & 7) * 32;
        const int rplus   = (kt >= 8) ? 1 : 0;
#pragma unroll
        for (int ks = 0; ks < 2; ks++) {
            uint32 zah[2][4], zal[2][4];
            const int khalf = colbase + ks * 16 + (lane >> 4) * 8;
#pragma unroll
            for (int mt = 0; mt < 2; mt++) {
                int row = zwM * 32 + mt * 16 + (lane & 15) + rplus;
                row = (row > 127) ? 127 : row;
                uint32 off = (uint32)(row * 264 + khalf) * 2;
                ldmx4(zah[mt], smbase + off);
                ldmx4(zal[mt], smbase + YPLW * 4 + off);
            }
            const int w0 = ks * 8 + t;
#pragma unroll
            for (int nt = 0; nt < 3; nt++) {
                int nn = zwN * 24 + nt * 8 + g;
                uint32 bh0 = Bz_h[w0 * 56 + nn], bh1 = Bz_h[(w0 + 4) * 56 + nn];
                uint32 bl0 = Bz_l[w0 * 56 + nn], bl1 = Bz_l[(w0 + 4) * 56 + nn];
#pragma unroll
                for (int mt = 0; mt < 2; mt++) {
                    mma_bf16(zacc[mt][nt], zah[mt], bh0, bh1);
                    mma_bf16(zacc[mt][nt], zah[mt], bl0, bl1);
                    mma_bf16(zacc[mt][nt], zal[mt], bh0, bh1);
                }
            }
        }
        __syncthreads();
    }

#pragma unroll
    for (int mt = 0; mt < 2; mt++) {
        int r0 = zwM * 32 + mt * 16 + g;
#pragma unroll
        for (int nt = 0; nt < 3; nt++) {
            int col = zwN * 24 + nt * 8 + 2 * t;
            float b0 = (col < 24)     ? gb0[col]     : fb0[col - 24];
            float b1 = (col + 1 < 24) ? gb0[col + 1] : fb0[col + 1 - 24];
            zs[r0][col]         = zacc[mt][nt][0] + b0;
            zs[r0][col + 1]     = zacc[mt][nt][1] + b1;
            zs[r0 + 8][col]     = zacc[mt][nt][2] + b0;
            zs[r0 + 8][col + 1] = zacc[mt][nt][3] + b1;
        }
    }
    __syncthreads();
    if (tid < 128) {
#pragma unroll
        for (int c = 0; c < 24; c++)
            zz[tid][c] = sigmoidf_(zs[tid][c]) * tanhf_(zs[tid][24 + c]);
    }
    __syncthreads();
    {
        int r = tid & 127, half = tid >> 7;
        long gmh = m0 + r;
        if (r < 127 && gmh < T2_) {
            float o[12];
#pragma unroll
            for (int j = 0; j < 12; j++) o[j] = sbs[half * 12 + j];
#pragma unroll
            for (int c = 0; c < 24; c++) {
                float zv = zz[r][c];
#pragma unroll
                for (int j = 0; j < 12; j++) o[j] += zv * sws[c][half * 12 + j];
            }
            float* ob = hOut + ((long)blockIdx.z * T2_ + gmh) * 24 + half * 12;
#pragma unroll
            for (int j = 0; j < 6; j++)
                *reinterpret_cast<float2*>(&ob[2 * j]) = make_float2(o[2 * j], o[2 * j + 1]);
        }
    }
}

// ============================================================================
// FUSED f1 + relu + f2 + exact softmax -> out.  Same structure as the causal
// fused kernel: f1 mainloop (K=128) -> bf16 hi/lo y-tile in smem -> in-CTA
// z-GEMM (K=256) vs Wf2 -> softmax -> fp32 store. a1 never touches DRAM.
// ============================================================================
__global__ __launch_bounds__(256, 1) void gemm_f1f2(
    const __nv_bfloat16* __restrict__ Ahi, const __nv_bfloat16* __restrict__ Alo,
    const uint32* __restrict__ B1hi, const uint32* __restrict__ B1lo,
    const uint32* __restrict__ B2hi, const uint32* __restrict__ B2lo,
    const float* __restrict__ b1, const float* __restrict__ b2,
    float* __restrict__ out, int Mrows)
{
    constexpr int NREAL = 256;
    constexpr int K1    = 128;
    constexpr int LDA   = 128;
    constexpr int ASTR = 40;
    constexpr int APLW = 128 * ASTR / 2;
    constexpr int AW   = 6 * APLW;
    constexpr int BSTR = 264;
    constexpr int BPL  = 16 * BSTR;
    constexpr int YPLW = 128 * 132;      // y-plane words
    constexpr int ZB0  = 2 * YPLW;       // 33792
    constexpr int ZBPL = 16 * 264;       // 4224 words per B2 chunk plane
    extern __shared__ __align__(16) uint32 sm[];
    __shared__ float red[128][4];

    const int tid   = threadIdx.x;
    const int wid   = tid >> 5, lane = tid & 31;
    const int warpM = wid >> 2, warpN = wid & 3;
    const int g     = lane >> 2, t = lane & 3;
    const int m0    = blockIdx.x * 128;

    uint32 smbase;
    asm("{ .reg .u64 tmp; cvta.to.shared.u64 tmp, %1; cvt.u32.u64 %0, tmp; }"
        : "=r"(smbase) : "l"(sm));

    float acc[4][8][4];
#pragma unroll
    for (int i = 0; i < 4; i++)
#pragma unroll
        for (int j = 0; j < 8; j++)
#pragma unroll
            for (int k = 0; k < 4; k++) acc[i][j][k] = 0.f;

    const int nk = K1 / 32;  // 4

    auto fill = [&](int kt) {
        const int st = kt % 3;
        const int k0 = kt * 32;
#pragma unroll
        for (int m = 0; m < 2; m++) {
            const __nv_bfloat16* Asrc = m ? Alo : Ahi;
#pragma unroll
            for (int j = 0; j < 2; j++) {
                int c = tid + j * 256;
                int r = c >> 2, q = c & 3;
                int gm = m0 + r;
                uint32 d = smbase + ((st * 2 + m) * APLW + r * 20 + q * 4) * 4;
                cp16(d, Asrc + (long)gm * LDA + k0 + q * 8, gm < Mrows);
            }
        }
#pragma unroll
        for (int m = 0; m < 2; m++) {
            const uint32* Bsrc = m ? B1lo : B1hi;
#pragma unroll
            for (int j = 0; j < 4; j++) {
                int c = tid + j * 256;
                int p = c >> 6, q = c & 63;
                uint32 d = smbase + (AW + (st * 2 + m) * BPL + p * BSTR + q * 4) * 4;
                cp16(d, Bsrc + (long)(k0 / 2 + p) * NREAL + q * 4, true);
            }
        }
        cpcommit();
    };

    fill(0);
    fill(1);
    for (int kt = 0; kt < nk; kt++) {
        if (kt + 2 < nk) { fill(kt + 2); cpwait<2>(); }
        else if (kt + 1 < nk) { cpwait<1>(); }
        else { cpwait<0>(); }
        __syncthreads();
        const int st = kt % 3;
        const uint32 aBaseH = smbase + ((st * 2 + 0) * APLW) * 4;
        const uint32 aBaseL = smbase + ((st * 2 + 1) * APLW) * 4;
        const uint32* B_h = sm + AW + (st * 2 + 0) * BPL;
        const uint32* B_l = sm + AW + (st * 2 + 1) * BPL;
        const int arow = warpM * 64 + (lane & 15);
        const int acol = (lane >> 4) * 8;
#pragma unroll
        for (int ks = 0; ks < 2; ks++) {
            uint32 ah[4][4], al[4][4];
            const int khalf = ks * 16 + acol;
#pragma unroll
            for (int mt = 0; mt < 4; mt++) {
                uint32 off = ((arow + mt * 16) * ASTR + khalf) * 2;
                ldmx4(ah[mt], aBaseH + off);
                ldmx4(al[mt], aBaseL + off);
            }
            const int w0 = ks * 8 + t;
#pragma unroll
            for (int nt = 0; nt < 8; nt++) {
                int nn = warpN * 64 + nt * 8 + g;
                uint32 bh0 = B_h[w0 * BSTR + nn], bh1 = B_h[(w0 + 4) * BSTR + nn];
                uint32 bl0 = B_l[w0 * BSTR + nn], bl1 = B_l[(w0 + 4) * BSTR + nn];
#pragma unroll
                for (int mt = 0; mt < 4; mt++) {
                    mma_bf16(acc[mt][nt], ah[mt], bh0, bh1);
                    mma_bf16(acc[mt][nt], ah[mt], bl0, bl1);
                    mma_bf16(acc[mt][nt], al[mt], bh0, bh1);
                }
            }
        }
        __syncthreads();
    }

    // prefetch first Wf2 chunk (targets >= ZB0, disjoint from y-store below)
    auto fillz = [&](int kt) {
        const int st = kt & 1;
#pragma unroll
        for (int m = 0; m < 2; m++) {
            const uint32* src = m ? B2lo : B2hi;
#pragma unroll
            for (int j = 0; j < 4; j++) {
                int c = tid + j * 256;
                int p = c >> 6, q = c & 63;
                uint32 d = smbase + (ZB0 + (st * 2 + m) * ZBPL + p * BSTR + q * 4) * 4;
                cp16(d, src + (long)(kt * 16 + p) * NREAL + q * 4, true);
            }
        }
        cpcommit();
    };
    fillz(0);

    // f1 epilogue: +b1, relu, bf16 hi/lo split -> y tile (row stride 264 halves)
#pragma unroll
    for (int mt = 0; mt < 4; mt++) {
        int r0 = warpM * 64 + mt * 16 + g;
#pragma unroll
        for (int nt = 0; nt < 8; nt++) {
            int c = warpN * 64 + nt * 8 + 2 * t;
            float bb0 = b1[c], bb1 = b1[c + 1];
            float v00 = fmaxf(acc[mt][nt][0] + bb0, 0.f);
            float v01 = fmaxf(acc[mt][nt][1] + bb1, 0.f);
            float v10 = fmaxf(acc[mt][nt][2] + bb0, 0.f);
            float v11 = fmaxf(acc[mt][nt][3] + bb1, 0.f);
            __nv_bfloat162 h0(__float2bfloat16(v00), __float2bfloat16(v01));
            __nv_bfloat162 l0(__float2bfloat16(v00 - __bfloat162float(h0.x)),
                              __float2bfloat16(v01 - __bfloat162float(h0.y)));
            __nv_bfloat162 h1(__float2bfloat16(v10), __float2bfloat16(v11));
            __nv_bfloat162 l1(__float2bfloat16(v10 - __bfloat162float(h1.x)),
                              __float2bfloat16(v11 - __bfloat162float(h1.y)));
            sm[r0 * 132 + (c >> 1)]              = *reinterpret_cast<uint32*>(&h0);
            sm[YPLW + r0 * 132 + (c >> 1)]       = *reinterpret_cast<uint32*>(&l0);
            sm[(r0 + 8) * 132 + (c >> 1)]        = *reinterpret_cast<uint32*>(&h1);
            sm[YPLW + (r0 + 8) * 132 + (c >> 1)] = *reinterpret_cast<uint32*>(&l1);
        }
    }
    // re-zero acc for f2
#pragma unroll
    for (int i = 0; i < 4; i++)
#pragma unroll
        for (int j = 0; j < 8; j++)
#pragma unroll
            for (int k = 0; k < 4; k++) acc[i][j][k] = 0.f;
    __syncthreads();

    // z-GEMM: [128 x 256 x 256] vs Wf2; same warp layout as mainloop.
    for (int kt = 0; kt < 8; kt++) {
        if (kt + 1 < 8) { fillz(kt + 1); cpwait<1>(); } else { cpwait<0>(); }
        __syncthreads();
        const int st = kt & 1;
        const uint32* Bz_h = sm + ZB0 + (st * 2 + 0) * ZBPL;
        const uint32* Bz_l = sm + ZB0 + (st * 2 + 1) * ZBPL;
        const int arow = warpM * 64 + (lane & 15);
        const int acol = (lane >> 4) * 8;
#pragma unroll
        for (int ks = 0; ks < 2; ks++) {
            uint32 ah[4][4], al[4][4];
            const int khalf = kt * 32 + ks * 16 + acol;
#pragma unroll
            for (int mt = 0; mt < 4; mt++) {
                uint32 off = (uint32)((arow + mt * 16) * 264 + khalf) * 2;
                ldmx4(ah[mt], smbase + off);
                ldmx4(al[mt], smbase + YPLW * 4 + off);
            }
            const int w0 = ks * 8 + t;
#pragma unroll
            for (int nt = 0; nt < 8; nt++) {
                int nn = warpN * 64 + nt * 8 + g;
                uint32 bh0 = Bz_h[w0 * BSTR + nn], bh1 = Bz_h[(w0 + 4) * BSTR + nn];
                uint32 bl0 = Bz_l[w0 * BSTR + nn], bl1 = Bz_l[(w0 + 4) * BSTR + nn];
#pragma unroll
                for (int mt = 0; mt < 4; mt++) {
                    mma_bf16(acc[mt][nt], ah[mt], bh0, bh1);
                    mma_bf16(acc[mt][nt], ah[mt], bl0, bl1);
                    mma_bf16(acc[mt][nt], al[mt], bh0, bh1);
                }
            }
        }
        __syncthreads();
    }

    // f2 bias
#pragma unroll
    for (int mt = 0; mt < 4; mt++)
#pragma unroll
        for (int nt = 0; nt < 8; nt++) {
            int gcol = warpN * 64 + nt * 8 + 2 * t;
            float bb0 = b2[gcol], bb1 = b2[gcol + 1];
            acc[mt][nt][0] += bb0; acc[mt][nt][1] += bb1;
            acc[mt][nt][2] += bb0; acc[mt][nt][3] += bb1;
        }

    // exact fp32 softmax over 256 cols (rows complete within CTA)
    {
        float rmax[4][2], rsum[4][2];
#pragma unroll
        for (int mt = 0; mt < 4; mt++)
#pragma unroll
            for (int h = 0; h < 2; h++) {
                float m = -1e30f;
#pragma unroll
                for (int nt = 0; nt < 8; nt++)
                    m = fmaxf(m, fmaxf(acc[mt][nt][2 * h], acc[mt][nt][2 * h + 1]));
                m = fmaxf(m, __shfl_xor_sync(0xffffffffu, m, 1));
                m = fmaxf(m, __shfl_xor_sync(0xffffffffu, m, 2));
                rmax[mt][h] = m;
            }
        if (t == 0)
#pragma unroll
            for (int mt = 0; mt < 4; mt++)
#pragma unroll
                for (int h = 0; h < 2; h++)
                    red[warpM * 64 + mt * 16 + g + h * 8][warpN] = rmax[mt][h];
        __syncthreads();
#pragma unroll
        for (int mt = 0; mt < 4; mt++)
#pragma unroll
            for (int h = 0; h < 2; h++) {
                int r = warpM * 64 + mt * 16 + g + h * 8;
                rmax[mt][h] = fmaxf(fmaxf(red[r][0], red[r][1]),
                                    fmaxf(red[r][2], red[r][3]));
            }
        __syncthreads();
#pragma unroll
        for (int mt = 0; mt < 4; mt++)
#pragma unroll
            for (int h = 0; h < 2; h++) {
                float s = 0.f;
#pragma unroll
                for (int nt = 0; nt < 8; nt++) {
                    float e0 = __expf(acc[mt][nt][2 * h]     - rmax[mt][h]);
                    float e1 = __expf(acc[mt][nt][2 * h + 1] - rmax[mt][h]);
                    acc[mt][nt][2 * h] = e0; acc[mt][nt][2 * h + 1] = e1;
                    s += e0 + e1;
                }
                s += __shfl_xor_sync(0xffffffffu, s, 1);
                s += __shfl_xor_sync(0xffffffffu, s, 2);
                rsum[mt][h] = s;
            }
        if (t == 0)
#pragma unroll
            for (int mt = 0; mt < 4; mt++)
#pragma unroll
                for (int h = 0; h < 2; h++)
                    red[warpM * 64 + mt * 16 + g + h * 8][warpN] = rsum[mt][h];
        __syncthreads();
#pragma unroll
        for (int mt = 0; mt < 4; mt++)
#pragma unroll
            for (int h = 0; h < 2; h++) {
                int r = warpM * 64 + mt * 16 + g + h * 8;
                float s = red[r][0] + red[r][1] + red[r][2] + red[r][3];
                float inv = 1.f / s;
#pragma unroll
                for (int nt = 0; nt < 8; nt++) {
                    acc[mt][nt][2 * h]     *= inv;
                    acc[mt][nt][2 * h + 1] *= inv;
                }
            }
    }

    // store probabilities
#pragma unroll
    for (int mt = 0; mt < 4; mt++) {
        int gm = m0 + warpM * 64 + mt * 16 + g;
#pragma unroll
        for (int nt = 0; nt < 8; nt++) {
            int gcol = warpN * 64 + nt * 8 + 2 * t;
            if (gm < Mrows)
                *reinterpret_cast<float2*>(&out[(long)gm * NREAL + gcol]) =
                    make_float2(acc[mt][nt][0], acc[mt][nt][1]);
            if (gm + 8 < Mrows)
                *reinterpret_cast<float2*>(&out[(long)(gm + 8) * NREAL + gcol]) =
                    make_float2(acc[mt][nt][2], acc[mt][nt][3]);
        }
    }
}

// ============================================================================
// fp32 -> hi/lo bf16 split
// ============================================================================
__global__ void split_bf16_vec(const float* __restrict__ s,
                               __nv_bfloat16* __restrict__ hi,
                               __nv_bfloat16* __restrict__ lo, long n)
{
    long i = ((long)blockIdx.x * 256 + threadIdx.x) * 4;
    if (i >= n) return;
    float4 v = *reinterpret_cast<const float4*>(s + i);
    __nv_bfloat16 h0 = __float2bfloat16(v.x), h1 = __float2bfloat16(v.y);
    __nv_bfloat16 h2 = __float2bfloat16(v.z), h3 = __float2bfloat16(v.w);
    __nv_bfloat16 l0 = __float2bfloat16(v.x - __bfloat162float(h0));
    __nv_bfloat16 l1 = __float2bfloat16(v.y - __bfloat162float(h1));
    __nv_bfloat16 l2 = __float2bfloat16(v.z - __bfloat162float(h2));
    __nv_bfloat16 l3 = __float2bfloat16(v.w - __bfloat162float(h3));
    reinterpret_cast<__nv_bfloat162*>(hi + i)[0] = __nv_bfloat162(h0, h1);
    reinterpret_cast<__nv_bfloat162*>(hi + i)[1] = __nv_bfloat162(h2, h3);
    reinterpret_cast<__nv_bfloat162*>(lo + i)[0] = __nv_bfloat162(l0, l1);
    reinterpret_cast<__nv_bfloat162*>(lo + i)[1] = __nv_bfloat162(l2, l3);
}

// ============================================================================
// One-shot weight prep
// ============================================================================
__device__ __forceinline__ void pair_store(float w0, float w1,
                                           uint32* bhi, uint32* blo, int idx)
{
    __nv_bfloat16 h0 = __float2bfloat16(w0), h1 = __float2bfloat16(w1);
    __nv_bfloat16 l0 = __float2bfloat16(w0 - __bfloat162float(h0));
    __nv_bfloat16 l1 = __float2bfloat16(w1 - __bfloat162float(h1));
    __nv_bfloat162 hw(h0, h1), lw(l0, l1);
    bhi[idx] = *reinterpret_cast<uint32*>(&hw);
    blo[idx] = *reinterpret_cast<uint32*>(&lw);
}

__global__ void prep_weights(
    const float* __restrict__ cauW, const float* __restrict__ f1W,
    const float* __restrict__ f2W,
    const float* __restrict__ gW, const float* __restrict__ fW,
    uint32* __restrict__ cauHi, uint32* __restrict__ cauLo,
    uint32* __restrict__ f1Hi,  uint32* __restrict__ f1Lo,
    uint32* __restrict__ f2Hi,  uint32* __restrict__ f2Lo,
    uint32* __restrict__ g0Hi,  uint32* __restrict__ g0Lo)
{
    int bid = blockIdx.x, tid = threadIdx.x;
    if (bid < 256) {
        int idx = bid * 256 + tid;
        int p = idx >> 8, n = idx & 255;
        pair_store(cauW[(2 * p) * 256 + n], cauW[(2 * p + 1) * 256 + n], cauHi, cauLo, idx);
    } else if (bid < 320) {
        int idx = (bid - 256) * 256 + tid;
        int p = idx >> 8, n = idx & 255;
        pair_store(f1W[(2 * p) * 256 + n], f1W[(2 * p + 1) * 256 + n], f1Hi, f1Lo, idx);
    } else if (bid < 448) {
        int idx = (bid - 320) * 256 + tid;
        int p = idx >> 8, n = idx & 255;
        pair_store(f2W[(2 * p) * 256 + n], f2W[(2 * p + 1) * 256 + n], f2Hi, f2Lo, idx);
    } else {
        int idx = (bid - 448) * 256 + tid;
        if (idx < 256 * 48) {
            int p = idx / 48, n = idx % 48;
            const float* src = (n < 24) ? gW : fW;
            int nn = (n < 24) ? n : n - 24;
            pair_store(src[(2 * p) * 24 + nn], src[(2 * p + 1) * 24 + nn], g0Hi, g0Lo, idx);
        }
    }
}

// ============================================================================
// Fused dilated gated layer (24 ch, f32x2) — weight-reuse (R15 best variant).
// ============================================================================
#define DGT 256
__global__ __launch_bounds__(256, 3) void dilated_gated(
    const float* __restrict__ hin, float* __restrict__ hout,
    const float* __restrict__ gateW, const float* __restrict__ gateB,
    const float* __restrict__ filtW, const float* __restrict__ filtB,
    const float* __restrict__ scaleW, const float* __restrict__ scaleB,
    int layer, int Tin, int Tout, int d)
{
    extern __shared__ __align__(16) float smf[];
    float* xs0 = smf;
    float* xs1 = smf + DGT * 25;
    ULL*   wb  = reinterpret_cast<ULL*>(smf + 2 * DGT * 25);
    ULL* gp0W = wb;
    ULL* gp1W = wb + 288;
    ULL* fp0W = wb + 576;
    ULL* fp1W = wb + 864;
    ULL* spW  = wb + 1152;
    ULL* gb2W = wb + 1440;
    ULL* fb2W = wb + 1452;
    ULL* sb2W = wb + 1464;
    float* zzW = smf;

    const int tid = threadIdx.x;
    const int b   = blockIdx.y;
    const int t0  = blockIdx.x * DGT;
    const int wbase = layer * 1152;
    for (int i = tid; i < 288; i += 256) {
        int c = i / 12, p = i % 12, o = 2 * p;
        gp0W[i] = pk2(gateW[wbase + c * 24 + o],       gateW[wbase + c * 24 + o + 1]);
        gp1W[i] = pk2(gateW[wbase + 576 + c * 24 + o], gateW[wbase + 576 + c * 24 + o + 1]);
        fp0W[i] = pk2(filtW[wbase + c * 24 + o],       filtW[wbase + c * 24 + o + 1]);
        fp1W[i] = pk2(filtW[wbase + 576 + c * 24 + o], filtW[wbase + 576 + c * 24 + o + 1]);
        spW[i]  = pk2(scaleW[layer * 576 + c * 24 + o], scaleW[layer * 576 + c * 24 + o + 1]);
    }
    if (tid < 12) {
        gb2W[tid] = pk2(gateB[layer * 24 + 2 * tid], gateB[layer * 24 + 2 * tid + 1]);
        fb2W[tid] = pk2(filtB[layer * 24 + 2 * tid], filtB[layer * 24 + 2 * tid + 1]);
        sb2W[tid] = pk2(scaleB[layer * 24 + 2 * tid], scaleB[layer * 24 + 2 * tid + 1]);
    }
    const float* hb = hin + (long)b * Tin * 24;
    for (int i = tid; i < DGT * 24; i += 256) {
        int r = i / 24, c = i % 24;
        int ta = t0 + r, tc = t0 + d + r;
        xs0[r * 25 + c] = (ta < Tin) ? hb[(long)ta * 24 + c] : 0.f;
        xs1[r * 25 + c] = (tc < Tin) ? hb[(long)tc * 24 + c] : 0.f;
    }
    __syncthreads();

    const int r    = tid & 127;
    const int half = tid >> 7;
    ULL gA[2][6], fA[2][6];
#pragma unroll
    for (int p = 0; p < 6; p++) {
        ULL gb = gb2W[half * 6 + p], fb = fb2W[half * 6 + p];
        gA[0][p] = gb; gA[1][p] = gb;
        fA[0][p] = fb; fA[1][p] = fb;
    }
#pragma unroll
    for (int c = 0; c < 24; c++) {
        ULL xa0 = dup2(xs0[r * 25 + c]);
        ULL xa1 = dup2(xs1[r * 25 + c]);
        ULL xb0 = dup2(xs0[(r + 128) * 25 + c]);
        ULL xb1 = dup2(xs1[(r + 128) * 25 + c]);
#pragma unroll
        for (int p = 0; p < 6; p++) {
            int pp = c * 12 + half * 6 + p;
            ULL g0 = gp0W[pp], g1 = gp1W[pp], f0 = fp0W[pp], f1 = fp1W[pp];
            ffma2(gA[0][p], xa0, g0); ffma2(gA[0][p], xa1, g1);
            ffma2(fA[0][p], xa0, f0); ffma2(fA[0][p], xa1, f1);
            ffma2(gA[1][p], xb0, g0); ffma2(gA[1][p], xb1, g1);
            ffma2(fA[1][p], xb0, f0); ffma2(fA[1][p], xb1, f1);
        }
    }
    float zv[2][12];
#pragma unroll
    for (int ts = 0; ts < 2; ts++)
#pragma unroll
        for (int p = 0; p < 6; p++) {
            float2 gv = unpk2(gA[ts][p]);
            float2 fv = unpk2(fA[ts][p]);
            zv[ts][2 * p]     = gatedact_(gv.x, fv.x);
            zv[ts][2 * p + 1] = gatedact_(gv.y, fv.y);
        }
    __syncthreads();
#pragma unroll
    for (int ts = 0; ts < 2; ts++) {
        int row = r + 128 * ts;
#pragma unroll
        for (int j = 0; j < 12; j++)
            zzW[row * 25 + half * 12 + j] = zv[ts][j];
    }
    __syncthreads();

    int t = t0 + tid;
    if (t >= Tout) return;
    ULL o2[12];
#pragma unroll
    for (int p = 0; p < 12; p++) o2[p] = sb2W[p];
#pragma unroll
    for (int c = 0; c < 24; c++) {
        ULL zd = dup2(zzW[tid * 25 + c]);
#pragma unroll
        for (int p = 0; p < 12; p++) ffma2(o2[p], zd, spW[c * 12 + p]);
    }
    ULL* ob = reinterpret_cast<ULL*>(hout + ((long)b * Tout + t) * 24);
#pragma unroll
    for (int p = 0; p < 12; p++) ob[p] = o2[p];
}

// ============================================================================
// Final residual add + res conv (24->128) + relu -> a0 as bf16 hi/lo split
// ============================================================================
__global__ __launch_bounds__(128) void resconv_relu(
    const float* __restrict__ prev8, const float* __restrict__ out8,
    const float* __restrict__ resW, const float* __restrict__ resB,
    __nv_bfloat16* __restrict__ a0hi, __nv_bfloat16* __restrict__ a0lo)
{
    __shared__ float ss[32][25];
    __shared__ float Ws[24][128];
    __shared__ float bs[128];
    const int tid = threadIdx.x;
    const int b   = blockIdx.y;
    const int t0  = blockIdx.x * 32;
    for (int i = tid; i < 24 * 128; i += 128) Ws[i / 128][i % 128] = resW[8 * 24 * 128 + i];
    bs[tid] = resB[8 * 128 + tid];
    const float* pb = prev8 + ((long)b * 15872 + 256) * 24;
    const float* ob = out8  + (long)b * TFIN * 24;
    for (int i = tid; i < 32 * 24; i += 128) {
        int r = i / 24, c = i % 24;
        long t = t0 + r;
        ss[r][c] = pb[t * 24 + c] + ob[t * 24 + c];
    }
    __syncthreads();
    long obase = ((long)b * TFIN + t0) * 128;
#pragma unroll 4
    for (int r = 0; r < 32; r++) {
        float a = bs[tid];
#pragma unroll
        for (int c = 0; c < 24; c++) a += ss[r][c] * Ws[c][tid];
        a = fmaxf(a, 0.f);
        __nv_bfloat16 h = __float2bfloat16(a);
        __nv_bfloat16 l = __float2bfloat16(a - __bfloat162float(h));
        a0hi[obase + (long)r * 128 + tid] = h;
        a0lo[obase + (long)r * 128 + tid] = l;
    }
}

// ============================================================================
extern "C" void kernel_launch(void* const* d_in, const int* in_sizes, int n_in,
                              void* d_out, int out_size)
{
    const float* x        = (const float*)d_in[0];
    const float* causal_W = (const float*)d_in[1];
    const float* causal_b = (const float*)d_in[2];
    const float* gW0      = (const float*)d_in[3];
    const float* gb0      = (const float*)d_in[4];
    const float* fW0      = (const float*)d_in[5];
    const float* fb0      = (const float*)d_in[6];
    const float* sW0      = (const float*)d_in[7];
    const float* sb0      = (const float*)d_in[8];
    const float* gateW    = (const float*)d_in[9];
    const float* gateB    = (const float*)d_in[10];
    const float* filtW    = (const float*)d_in[11];
    const float* filtB    = (const float*)d_in[12];
    const float* scaleW   = (const float*)d_in[13];
    const float* scaleB   = (const float*)d_in[14];
    const float* resW     = (const float*)d_in[15];
    const float* resB     = (const float*)d_in[16];
    const float* f1W      = (const float*)d_in[17];
    const float* f1b      = (const float*)d_in[18];
    const float* f2W      = (const float*)d_in[19];
    const float* f2b      = (const float*)d_in[20];
    float* out = (float*)d_out;

    __nv_bfloat16 *xhi, *xlo, *a0hi, *a0lo;
    float *hA, *hB;
    uint32 *WcauHi, *WcauLo, *Wg0Hi, *Wg0Lo, *Wf1Hi, *Wf1Lo, *Wf2Hi, *Wf2Lo;
    cudaGetSymbolAddress((void**)&xhi,  g_xhi);  cudaGetSymbolAddress((void**)&xlo,  g_xlo);
    cudaGetSymbolAddress((void**)&hA,   g_hA);   cudaGetSymbolAddress((void**)&hB,   g_hB);
    cudaGetSymbolAddress((void**)&a0hi, g_a0hi); cudaGetSymbolAddress((void**)&a0lo, g_a0lo);
    cudaGetSymbolAddress((void**)&WcauHi, g_WcauHi); cudaGetSymbolAddress((void**)&WcauLo, g_WcauLo);
    cudaGetSymbolAddress((void**)&Wg0Hi,  g_Wg0Hi);  cudaGetSymbolAddress((void**)&Wg0Lo,  g_Wg0Lo);
    cudaGetSymbolAddress((void**)&Wf1Hi,  g_Wf1Hi);  cudaGetSymbolAddress((void**)&Wf1Lo,  g_Wf1Lo);
    cudaGetSymbolAddress((void**)&Wf2Hi,  g_Wf2Hi);  cudaGetSymbolAddress((void**)&Wf2Lo,  g_Wf2Lo);

    const int SMEM_CAU  = (6 * 2560 + 6 * 16 * 264) * 4;               // 162816 B
    const int SMEM_F1F2 = (2 * 128 * 132 + 4 * 16 * 264) * 4;          // 202752 B
    const int SMEM_DG   = (2 * 256 * 25 + 2 * 1476) * 4;               // 63008 B
    cudaFuncSetAttribute((const void*)gemm_causal_gated, cudaFuncAttributeMaxDynamicSharedMemorySize, SMEM_CAU);
    cudaFuncSetAttribute((const void*)gemm_f1f2,         cudaFuncAttributeMaxDynamicSharedMemorySize, SMEM_F1F2);
    cudaFuncSetAttribute((const void*)dilated_gated,     cudaFuncAttributeMaxDynamicSharedMemorySize, SMEM_DG);

    // 0. preprocessing
    long nx = (long)B_ * T0_ * 256;
    split_bf16_vec<<<(int)(nx / 4 / 256), 256>>>(x, xhi, xlo, nx);               // 1
    prep_weights<<<496, 256>>>(causal_W, f1W, f2W, gW0, fW0,
                               WcauHi, WcauLo, Wf1Hi, Wf1Lo,
                               Wf2Hi, Wf2Lo, Wg0Hi, Wg0Lo);                      // 2

    // 1. FUSED causal conv + gated0 -> hA                                     // 3
    gemm_causal_gated<<<dim3(129, 1, B_), 256, SMEM_CAU>>>(
        xhi, xlo, WcauHi, WcauLo, causal_b,
        Wg0Hi, Wg0Lo, gb0, fb0, sW0, sb0, hA);

    // 2. nine dilated gated layers (ping-pong hA/hB)                          // 4..12
    int Tin = T2_;
    float* hin  = hA;
    float* hnew = hB;
    for (int i = 0; i < 9; i++) {
        int d = 2 << i;
        int Tout = Tin - d;
        dim3 g((Tout + DGT - 1) / DGT, B_);
        dilated_gated<<<g, 256, SMEM_DG>>>(hin, hnew, gateW, gateB, filtW, filtB,
                                           scaleW, scaleB, i, Tin, Tout, d);
        float* tmp = hin; hin = hnew; hnew = tmp;
        Tin = Tout;
    }
    // hin = layer-8 output (T=15360), hnew = layer-7 output (T=15872)

    // 3. residual add + res conv + relu -> a0 hi/lo
    resconv_relu<<<dim3(480, B_), 128>>>(hnew, hin, resW, resB, a0hi, a0lo);

    // 4. FUSED f1 + relu + f2 + softmax -> probabilities fp32 in d_out
    gemm_f1f2<<<dim3(960, 1, 1), 256, SMEM_F1F2>>>(
        a0hi, a0lo, Wf1Hi, Wf1Lo, Wf2Hi, Wf2Lo, f1b, f2b,
        out, B_ * TFIN);
}